// round 12
// baseline (speedup 1.0000x reference)
#include <cuda_runtime.h>
#include <cstdint>

typedef unsigned long long ull;

#define B 8
#define H 512
#define W 512

// ---------------- device scratch (allocation-free) ----------------
__device__ float g_kpre[B * H * W];
__device__ float g_edges[B * H * W];
__device__ ull   g_gxy[B * H * W];     // packed (gx, gy) per pixel
__device__ float g_k2s[72];
__device__ float g_kc[121];

// ---------------- f32x2 packed helpers (sm_100+) ----------------
__device__ __forceinline__ ull pack2(float lo, float hi) {
    ull r;
    asm("mov.b64 %0, {%1, %2};" : "=l"(r) : "f"(lo), "f"(hi));
    return r;
}
__device__ __forceinline__ float2 unpack2(ull v) {
    float2 r;
    asm("mov.b64 {%0, %1}, %2;" : "=f"(r.x), "=f"(r.y) : "l"(v));
    return r;
}
__device__ __forceinline__ void fma2(ull& acc, ull a, ull b) {
    asm("fma.rn.f32x2 %0, %1, %2, %0;" : "+l"(acc) : "l"(a), "l"(b));
}

// ---------------- border band decode: 64 segs/batch, 32-px segments, bw=3 ----------------
__device__ __forceinline__ void band_region(int id, int bw,
                                            int& oy0, int& ox0, int& oR, int& oC) {
    int seg = id >> 4, s = id & 15;
    if (seg == 0)      { oy0 = 0;      ox0 = 32 * s; oR = bw; oC = 32; }
    else if (seg == 1) { oy0 = H - bw; ox0 = 32 * s; oR = bw; oC = 32; }
    else if (seg == 2) { oy0 = 32 * s; ox0 = 0;      oR = 32; oC = bw; }
    else               { oy0 = 32 * s; ox0 = W - bw; oR = 32; oC = bw; }
}

// ---------------- kernel: compose k0 o k1 o sum16(k2) -> 11x11 (smem-staged) ----------------
__global__ void k_compose(const float* __restrict__ k0,
                          const float* __restrict__ k1,
                          const float* __restrict__ k2) {
    __shared__ float s_k2s[72];
    __shared__ float s_k0[200];
    __shared__ float s_k1[1600];
    __shared__ float s_K01[648]; // [ry(9)][rx(9)][c2(8)]
    const int tid = threadIdx.x;

    for (int i = tid; i < 200; i += 648) s_k0[i] = k0[i];
    for (int i = tid; i < 1600; i += 648) s_k1[i] = k1[i];
    if (tid < 72) {
        float s = 0.f;
#pragma unroll
        for (int o = 0; o < 16; ++o) s += k2[tid * 16 + o];
        s_k2s[tid] = s;
        g_k2s[tid] = s;
    }
    __syncthreads();

    if (tid < 648) {
        int c2 = tid & 7;
        int rx = (tid >> 3) % 9;
        int ry = tid / 72;
        float v = 0.f;
        int sy0 = ry - 4 > 0 ? ry - 4 : 0, sy1 = ry < 4 ? ry : 4;
        int sx0 = rx - 4 > 0 ? rx - 4 : 0, sx1 = rx < 4 ? rx : 4;
        for (int sy = sy0; sy <= sy1; ++sy)
            for (int sx = sx0; sx <= sx1; ++sx) {
                int ty = ry - sy, txx = rx - sx;
#pragma unroll
                for (int c1 = 0; c1 < 8; ++c1)
                    v += s_k0[(sy * 5 + sx) * 8 + c1] *
                         s_k1[((ty * 5 + txx) * 8 + c1) * 8 + c2];
            }
        s_K01[(ry * 9 + rx) * 8 + c2] = v;
    }
    __syncthreads();

    if (tid < 121) {
        int fx = tid % 11, fy = tid / 11;
        float v = 0.f;
        int ry0 = fy - 2 > 0 ? fy - 2 : 0, ry1 = fy < 8 ? fy : 8;
        int rx0 = fx - 2 > 0 ? fx - 2 : 0, rx1 = fx < 8 ? fx : 8;
        for (int ry = ry0; ry <= ry1; ++ry)
            for (int rx = rx0; rx <= rx1; ++rx) {
                int vy = fy - ry, vx = fx - rx;
#pragma unroll
                for (int c2 = 0; c2 < 8; ++c2)
                    v += s_K01[(ry * 9 + rx) * 8 + c2] *
                         s_k2s[(vy * 3 + vx) * 8 + c2];
            }
        g_kc[tid] = v;
    }
}

// ---------------- fused kernel: edges (in smem) -> grads; writes g_edges interior + g_gxy ----------------
__global__ void __launch_bounds__(256, 3)
k_edgegrad(const float* __restrict__ image,
           const float* __restrict__ dw,   // (3,3,1,8)
           const float* __restrict__ pw,   // (1,1,8,8)
           const float* __restrict__ wx,   // (3,3,1,32) -> [t*32+co]
           const float* __restrict__ wy) {
    __shared__ __align__(16) float s_img[36 * 36];
    __shared__ __align__(16) float s_e[34 * 34];
    __shared__ __align__(16) ull   s_e2[26 * 34];
    __shared__ __align__(16) ull   s_wx2[288];
    __shared__ __align__(16) ull   s_wy2[288];
    __shared__ __align__(16) ull   s_dw2[36];
    __shared__ __align__(16) ull   s_pw2[32];

    const int b = blockIdx.z;
    const int x0 = blockIdx.x * 32, y0 = blockIdx.y * 32;
    const int tid = threadIdx.x;

    for (int i = tid; i < 288; i += 256) {
        float a = wx[i], c = wy[i];
        s_wx2[i] = pack2(a, a);
        s_wy2[i] = pack2(c, c);
    }
    if (tid < 36) {
        float2 v = ((const float2*)dw)[tid];
        s_dw2[tid] = pack2(v.x, v.y);
    }
    if (tid >= 64 && tid < 96) {
        float2 v = ((const float2*)pw)[tid - 64];
        s_pw2[tid - 64] = pack2(v.x, v.y);
    }
    // image halo, origin (y0-2, x0-2)
    for (int i = tid; i < 36 * 36; i += 256) {
        int r = i / 36, c = i % 36;
        int gy = y0 - 2 + r, gx = x0 - 2 + c;
        float v = 0.f;
        if (gy >= 0 && gy < H && gx >= 0 && gx < W)
            v = image[((b * H) + gy) * W + gx];
        s_img[i] = v;
    }
    __syncthreads();

    // edges on the 34x34 halo (origin y0-1); OOB positions MUST stay 0
    for (int i = tid; i < 34 * 34; i += 256) {
        int r = i / 34, c = i % 34;
        int gy = y0 - 1 + r, gx = x0 - 1 + c;
        float ed = 0.f;
        if (gy >= 0 && gy < H && gx >= 0 && gx < W) {
            ull e1p[4] = {0ull, 0ull, 0ull, 0ull};
#pragma unroll
            for (int t = 0; t < 9; ++t) {
                float v = s_img[(r + t / 3) * 36 + c + t % 3];
                ull vv = pack2(v, v);
                fma2(e1p[0], vv, s_dw2[t * 4 + 0]);
                fma2(e1p[1], vv, s_dw2[t * 4 + 1]);
                fma2(e1p[2], vv, s_dw2[t * 4 + 2]);
                fma2(e1p[3], vv, s_dw2[t * 4 + 3]);
            }
            ull e2p[4] = {0ull, 0ull, 0ull, 0ull};
#pragma unroll
            for (int j = 0; j < 4; ++j) {
                float2 e = unpack2(e1p[j]);
                ull sa = pack2(e.x, e.x);
                ull sb = pack2(e.y, e.y);
                const int ca = (2 * j) * 4, cb = (2 * j + 1) * 4;
                fma2(e2p[0], sa, s_pw2[ca + 0]);
                fma2(e2p[1], sa, s_pw2[ca + 1]);
                fma2(e2p[2], sa, s_pw2[ca + 2]);
                fma2(e2p[3], sa, s_pw2[ca + 3]);
                fma2(e2p[0], sb, s_pw2[cb + 0]);
                fma2(e2p[1], sb, s_pw2[cb + 1]);
                fma2(e2p[2], sb, s_pw2[cb + 2]);
                fma2(e2p[3], sb, s_pw2[cb + 3]);
            }
            float s = 0.f;
#pragma unroll
            for (int k = 0; k < 4; ++k) {
                float2 rr = unpack2(e2p[k]);
                s += fmaxf(rr.x, 0.f) + fmaxf(rr.y, 0.f);
            }
            ed = __fdividef(s, 1.f + fabsf(s));
            // interior pixels: persist for k_final's center term
            if (r >= 1 && r <= 32 && c >= 1 && c <= 32)
                g_edges[((b * H) + gy) * W + gx] = ed;
        }
        s_e[i] = ed;
    }
    __syncthreads();
    // pack vertical pixel pairs (row r, row r+8)
    for (int i = tid; i < 26 * 34; i += 256)
        s_e2[i] = pack2(s_e[i], s_e[i + 8 * 34]);
    __syncthreads();

    const int tx = tid & 31, ty = tid >> 5;  // ty 0..7
    // pair A: rows (ty, ty+8); pair B: rows (ty+16, ty+24)

    ull tapA[9], tapB[9];
#pragma unroll
    for (int t = 0; t < 9; ++t) {
        tapA[t] = s_e2[(ty + t / 3) * 34 + tx + t % 3];
        tapB[t] = s_e2[(ty + 16 + t / 3) * 34 + tx + t % 3];
    }

    float gxA0 = 0.f, gxA1 = 0.f, gyA0 = 0.f, gyA1 = 0.f;
    float gxB0 = 0.f, gxB1 = 0.f, gyB0 = 0.f, gyB1 = 0.f;
#pragma unroll 1
    for (int co = 0; co < 32; co += 2) {
        ull axA0 = 0ull, axA1 = 0ull, ayA0 = 0ull, ayA1 = 0ull;
        ull axB0 = 0ull, axB1 = 0ull, ayB0 = 0ull, ayB1 = 0ull;
#pragma unroll
        for (int t = 0; t < 9; ++t) {
            ulonglong2 wxp = *(const ulonglong2*)(s_wx2 + t * 32 + co);
            ulonglong2 wyp = *(const ulonglong2*)(s_wy2 + t * 32 + co);
            fma2(axA0, tapA[t], wxp.x);
            fma2(axA1, tapA[t], wxp.y);
            fma2(ayA0, tapA[t], wyp.x);
            fma2(ayA1, tapA[t], wyp.y);
            fma2(axB0, tapB[t], wxp.x);
            fma2(axB1, tapB[t], wxp.y);
            fma2(ayB0, tapB[t], wyp.x);
            fma2(ayB1, tapB[t], wyp.y);
        }
        float2 r0, r1;
        r0 = unpack2(axA0); r1 = unpack2(axA1);
        gxA0 += fmaxf(r0.x, 0.f) + fmaxf(r1.x, 0.f);
        gxA1 += fmaxf(r0.y, 0.f) + fmaxf(r1.y, 0.f);
        r0 = unpack2(ayA0); r1 = unpack2(ayA1);
        gyA0 += fmaxf(r0.x, 0.f) + fmaxf(r1.x, 0.f);
        gyA1 += fmaxf(r0.y, 0.f) + fmaxf(r1.y, 0.f);
        r0 = unpack2(axB0); r1 = unpack2(axB1);
        gxB0 += fmaxf(r0.x, 0.f) + fmaxf(r1.x, 0.f);
        gxB1 += fmaxf(r0.y, 0.f) + fmaxf(r1.y, 0.f);
        r0 = unpack2(ayB0); r1 = unpack2(ayB1);
        gyB0 += fmaxf(r0.x, 0.f) + fmaxf(r1.x, 0.f);
        gyB1 += fmaxf(r0.y, 0.f) + fmaxf(r1.y, 0.f);
    }

    const float gxv[4] = {gxA0, gxA1, gxB0, gxB1};
    const float gyv[4] = {gyA0, gyA1, gyB0, gyB1};
#pragma unroll
    for (int k = 0; k < 4; ++k) {
        const int py = ty + 8 * k;
        g_gxy[((b * H) + (y0 + py)) * W + (x0 + tx)] = pack2(gxv[k], gyv[k]);
    }
}

// ---------------- kernel: kpre = conv11x11(u, g_kc) * kappa_kernel ----------------
__global__ void __launch_bounds__(256, 3)
k_kpre(const float* __restrict__ u, const float* __restrict__ kap) {
    __shared__ __align__(16) float s_t[42 * 42];
    __shared__ __align__(16) ull   s_K2[121];

    const int b = blockIdx.z;
    const int x0 = blockIdx.x * 32, y0 = blockIdx.y * 32;
    const int tid = threadIdx.x;

    for (int i = tid; i < 121; i += 256) {
        float w = g_kc[i];
        s_K2[i] = pack2(w, w);
    }
    for (int i = tid; i < 42 * 42; i += 256) {
        int r = i / 42, c = i % 42;
        int gy = y0 - 5 + r, gx = x0 - 5 + c;
        float v = 0.f;
        if (gy >= 0 && gy < H && gx >= 0 && gx < W)
            v = u[((b * H) + gy) * W + gx];
        s_t[i] = v;
    }
    __syncthreads();

    const int tx = tid & 31, ty = tid >> 5;
    const int r0 = ty * 4;

    ull acc[2] = {0ull, 0ull};

#pragma unroll 1
    for (int dx = 0; dx < 11; ++dx) {
        float t[14];
        const float* col = s_t + r0 * 42 + tx + dx;
#pragma unroll
        for (int i = 0; i < 14; ++i) t[i] = col[i * 42];
        ull pk[13];
#pragma unroll
        for (int i = 0; i < 13; ++i) pk[i] = pack2(t[i], t[i + 1]);
#pragma unroll
        for (int dy = 0; dy < 11; ++dy) {
            ull w = s_K2[dy * 11 + dx];
            fma2(acc[0], pk[dy],     w);
            fma2(acc[1], pk[dy + 2], w);
        }
    }

    const int x = x0 + tx;
#pragma unroll
    for (int p = 0; p < 2; ++p) {
        float2 r = unpack2(acc[p]);
        int y = y0 + r0 + 2 * p;
        g_kpre[((b * H) + y) * W + x]     = r.x * kap[y * W + x];
        g_kpre[((b * H) + y + 1) * W + x] = r.y * kap[(y + 1) * W + x];
    }
}

// ---------------- fused band kernel: u -> c0 -> c1 -> c2k*kap in smem (band 3, dual-acc c1) ----------------
__global__ void __launch_bounds__(256, 2)
k_band(const float* __restrict__ u,
       const float* __restrict__ k0,
       const float* __restrict__ k1,
       const float* __restrict__ kap) {
    __shared__ __align__(16) float s_u[546];
    __shared__ __align__(16) ull   s_w0[100];
    __shared__ __align__(16) float s_w1[1600];
    __shared__ float s_k2[72];
    __shared__ __align__(16) float s_c0[8 * 342];
    __shared__ __align__(16) float s_c1[8 * 170];

    const int b = blockIdx.y;
    int oy0, ox0, oR, oC;
    band_region(blockIdx.x, 3, oy0, ox0, oR, oC);
    const int RWu = oC + 10;
    const int RW0 = oC + 6;
    const int RW1 = oC + 2;
    const int Nu = (oR + 10) * RWu;
    const int N0 = (oR + 6) * RW0;
    const int N1 = (oR + 2) * RW1;
    const int tid = threadIdx.x;

    for (int i = tid; i < 100; i += 256) {
        float2 w = ((const float2*)k0)[i];
        s_w0[i] = pack2(w.x, w.y);
    }
    for (int i = tid; i < 1600; i += 256) s_w1[i] = k1[i];
    for (int i = tid; i < 72; i += 256) s_k2[i] = g_k2s[i];
    for (int i = tid; i < Nu; i += 256) {
        int r = i / RWu, c = i % RWu;
        int gy = oy0 - 5 + r, gx = ox0 - 5 + c;
        float v = 0.f;
        if (gy >= 0 && gy < H && gx >= 0 && gx < W)
            v = u[((b * H) + gy) * W + gx];
        s_u[i] = v;
    }
    __syncthreads();

    for (int i = tid; i < N0; i += 256) {
        int r = i / RW0, c = i % RW0;
        int gy = oy0 - 3 + r, gx = ox0 - 3 + c;
        ull acc[4] = {0ull, 0ull, 0ull, 0ull};
        if (gy >= 0 && gy < H && gx >= 0 && gx < W) {
#pragma unroll 1
            for (int t = 0; t < 25; ++t) {
                int dy = t / 5, dx = t % 5;
                float v = s_u[(r + dy) * RWu + c + dx];
                ull vv = pack2(v, v);
                fma2(acc[0], vv, s_w0[t * 4 + 0]);
                fma2(acc[1], vv, s_w0[t * 4 + 1]);
                fma2(acc[2], vv, s_w0[t * 4 + 2]);
                fma2(acc[3], vv, s_w0[t * 4 + 3]);
            }
        }
        float2 a0 = unpack2(acc[0]);
        float2 a1 = unpack2(acc[1]);
        float2 a2 = unpack2(acc[2]);
        float2 a3 = unpack2(acc[3]);
        s_c0[0 * 342 + i] = a0.x;  s_c0[1 * 342 + i] = a0.y;
        s_c0[2 * 342 + i] = a1.x;  s_c0[3 * 342 + i] = a1.y;
        s_c0[4 * 342 + i] = a2.x;  s_c0[5 * 342 + i] = a2.y;
        s_c0[6 * 342 + i] = a3.x;  s_c0[7 * 342 + i] = a3.y;
    }
    __syncthreads();

    for (int i = tid; i < N1; i += 256) {
        int r = i / RW1, c = i % RW1;
        int gy = oy0 - 1 + r, gx = ox0 - 1 + c;
        ull accA[4] = {0ull, 0ull, 0ull, 0ull};
        ull accB[4] = {0ull, 0ull, 0ull, 0ull};
        if (gy >= 0 && gy < H && gx >= 0 && gx < W) {
            // dual accumulator sets halve the fma2 dependency chain
#pragma unroll 1
            for (int t = 0; t < 12; ++t) {
                int dy = t / 5, dx = t % 5;
                const float* wp = s_w1 + t * 64;
                const int base = (r + dy) * RW0 + c + dx;
#pragma unroll
                for (int ci = 0; ci < 8; ++ci) {
                    ulonglong2 wA = *(const ulonglong2*)(wp + ci * 8);
                    ulonglong2 wB = *(const ulonglong2*)(wp + ci * 8 + 4);
                    float v = s_c0[ci * 342 + base];
                    ull p = pack2(v, v);
                    fma2(accA[0], p, wA.x); fma2(accA[1], p, wA.y);
                    fma2(accA[2], p, wB.x); fma2(accA[3], p, wB.y);
                }
            }
#pragma unroll 1
            for (int t = 12; t < 25; ++t) {
                int dy = t / 5, dx = t % 5;
                const float* wp = s_w1 + t * 64;
                const int base = (r + dy) * RW0 + c + dx;
#pragma unroll
                for (int ci = 0; ci < 8; ++ci) {
                    ulonglong2 wA = *(const ulonglong2*)(wp + ci * 8);
                    ulonglong2 wB = *(const ulonglong2*)(wp + ci * 8 + 4);
                    float v = s_c0[ci * 342 + base];
                    ull p = pack2(v, v);
                    fma2(accB[0], p, wA.x); fma2(accB[1], p, wA.y);
                    fma2(accB[2], p, wB.x); fma2(accB[3], p, wB.y);
                }
            }
        }
        float2 a0A = unpack2(accA[0]), a0B = unpack2(accB[0]);
        float2 a1A = unpack2(accA[1]), a1B = unpack2(accB[1]);
        float2 a2A = unpack2(accA[2]), a2B = unpack2(accB[2]);
        float2 a3A = unpack2(accA[3]), a3B = unpack2(accB[3]);
        s_c1[0 * 170 + i] = a0A.x + a0B.x;  s_c1[1 * 170 + i] = a0A.y + a0B.y;
        s_c1[2 * 170 + i] = a1A.x + a1B.x;  s_c1[3 * 170 + i] = a1A.y + a1B.y;
        s_c1[4 * 170 + i] = a2A.x + a2B.x;  s_c1[5 * 170 + i] = a2A.y + a2B.y;
        s_c1[6 * 170 + i] = a3A.x + a3B.x;  s_c1[7 * 170 + i] = a3A.y + a3B.y;
    }
    __syncthreads();

    for (int i = tid; i < oR * oC; i += 256) {
        int r = i / oC, c = i % oC;
        float acc = 0.f;
#pragma unroll
        for (int t = 0; t < 9; ++t) {
            int dy = t / 3, dx = t % 3;
            const int idx = (r + dy) * RW1 + c + dx;
#pragma unroll
            for (int ci = 0; ci < 8; ++ci)
                acc = fmaf(s_c1[ci * 170 + idx], s_k2[t * 8 + ci], acc);
        }
        int y = oy0 + r, x = ox0 + c;
        g_kpre[((b * H) + y) * W + x] = acc * kap[y * W + x];
    }
}

// ---------------- final-lite: diffs + smoother + sum ----------------
__global__ void __launch_bounds__(256, 3)
k_final(const float* __restrict__ u,
        const float* __restrict__ ws,  // (5,5,1,1)
        float* __restrict__ out) {
    __shared__ __align__(16) float s_u[34 * 34];
    __shared__ __align__(16) ull   s_kp2[28 * 36];
    __shared__ __align__(16) ull   s_ws2[25];

    const int b = blockIdx.z;
    const int x0 = blockIdx.x * 32, y0 = blockIdx.y * 32;
    const int tid = threadIdx.x;

    if (tid < 25) {
        float w = ws[tid];
        s_ws2[tid] = pack2(w, w);
    }
    for (int i = tid; i < 34 * 34; i += 256) {
        int r = i / 34, c = i % 34;
        int gy = y0 - 1 + r, gx = x0 - 1 + c;
        float v = 0.f;
        if (gy >= 0 && gy < H && gx >= 0 && gx < W)
            v = u[((b * H) + gy) * W + gx];
        s_u[i] = v;
    }
    for (int i = tid; i < 28 * 36; i += 256) {
        int r = i / 36, c = i % 36;
        int gy = y0 - 2 + r, gx = x0 - 2 + c;
        float p0 = 0.f, p1 = 0.f;
        if (gx >= 0 && gx < W) {
            if (gy >= 0 && gy < H)         p0 = g_kpre[((b * H) + gy) * W + gx];
            if (gy + 8 >= 0 && gy + 8 < H) p1 = g_kpre[((b * H) + gy + 8) * W + gx];
        }
        s_kp2[i] = pack2(p0, p1);
    }
    __syncthreads();

    const int tx = tid & 31, ty = tid >> 5;

    ull kaccA = 0ull, kaccB = 0ull;
#pragma unroll
    for (int t = 0; t < 25; ++t) {
        ull w = s_ws2[t];
        fma2(kaccA, s_kp2[(ty + t / 5) * 36 + tx + t % 5], w);
        fma2(kaccB, s_kp2[(ty + 16 + t / 5) * 36 + tx + t % 5], w);
    }
    float2 kpA = unpack2(kaccA), kpB = unpack2(kaccB);
    const float kvv[4] = {kpA.x, kpA.y, kpB.x, kpB.y};

#pragma unroll
    for (int k = 0; k < 4; ++k) {
        const int py = ty + 8 * k;
        const int gidx = ((b * H) + (y0 + py)) * W + (x0 + tx);
        const int ec = (py + 1) * 34 + tx + 1;
        float uc = s_u[ec];
        float xp = uc - s_u[ec - 1];
        float yp = uc - s_u[ec + 34];

        float2 g = unpack2(g_gxy[gidx]);
        float ev = g_edges[gidx];

        // fxn = fyn = 0 exactly (gx, gy are sums of relus)
        out[gidx] = uc + g.x * xp + g.y * yp + ev + kvv[k];
    }
}

// ---------------- launch ----------------
extern "C" void kernel_launch(void* const* d_in, const int* in_sizes, int n_in,
                              void* d_out, int out_size) {
    (void)in_sizes; (void)n_in; (void)out_size;
    const float* u     = (const float*)d_in[0];
    const float* image = (const float*)d_in[1];
    const float* wx    = (const float*)d_in[2];
    const float* wy    = (const float*)d_in[3];
    const float* dw    = (const float*)d_in[4];
    const float* pw    = (const float*)d_in[5];
    const float* k0    = (const float*)d_in[6];
    const float* k1    = (const float*)d_in[7];
    const float* k2    = (const float*)d_in[8];
    const float* ws    = (const float*)d_in[9];
    const float* kap   = (const float*)d_in[10];
    float* out = (float*)d_out;

    dim3 gridT(W / 32, H / 32, B);

    k_compose<<<1, 648>>>(k0, k1, k2);
    k_edgegrad<<<gridT, dim3(256)>>>(image, dw, pw, wx, wy);
    k_kpre<<<gridT, dim3(256)>>>(u, kap);
    k_band<<<dim3(64, B), dim3(256)>>>(u, k0, k1, kap);
    k_final<<<gridT, dim3(256)>>>(u, ws, out);
}

// round 13
// speedup vs baseline: 1.0085x; 1.0085x over previous
#include <cuda_runtime.h>
#include <cstdint>

typedef unsigned long long ull;

#define B 8
#define H 512
#define W 512

// ---------------- device scratch (allocation-free) ----------------
__device__ float g_kpre[B * H * W];
__device__ float g_edges[B * H * W];
__device__ ull   g_gxy[B * H * W];     // packed (gx, gy) per pixel
__device__ float g_k2s[72];
__device__ float g_kc[121];

// ---------------- f32x2 packed helpers (sm_100+) ----------------
__device__ __forceinline__ ull pack2(float lo, float hi) {
    ull r;
    asm("mov.b64 %0, {%1, %2};" : "=l"(r) : "f"(lo), "f"(hi));
    return r;
}
__device__ __forceinline__ float2 unpack2(ull v) {
    float2 r;
    asm("mov.b64 {%0, %1}, %2;" : "=f"(r.x), "=f"(r.y) : "l"(v));
    return r;
}
__device__ __forceinline__ void fma2(ull& acc, ull a, ull b) {
    asm("fma.rn.f32x2 %0, %1, %2, %0;" : "+l"(acc) : "l"(a), "l"(b));
}

// ---------------- border band decode: 64 segs/batch, 32-px segments, bw=3 ----------------
__device__ __forceinline__ void band_region(int id, int bw,
                                            int& oy0, int& ox0, int& oR, int& oC) {
    int seg = id >> 4, s = id & 15;
    if (seg == 0)      { oy0 = 0;      ox0 = 32 * s; oR = bw; oC = 32; }
    else if (seg == 1) { oy0 = H - bw; ox0 = 32 * s; oR = bw; oC = 32; }
    else if (seg == 2) { oy0 = 32 * s; ox0 = 0;      oR = 32; oC = bw; }
    else               { oy0 = 32 * s; ox0 = W - bw; oR = 32; oC = bw; }
}

// ---------------- kernel 1: edges everywhere; block (0,0,0) also runs compose ----------------
__global__ void __launch_bounds__(256, 3)
k_edges(const float* __restrict__ image,
        const float* __restrict__ dw,   // (3,3,1,8)
        const float* __restrict__ pw,   // (1,1,8,8)
        const float* __restrict__ k0,   // (5,5,1,8)
        const float* __restrict__ k1,   // (5,5,8,8)
        const float* __restrict__ k2) { // (3,3,8,16)
    __shared__ __align__(16) float s_img[34 * 34];
    __shared__ __align__(16) ull   s_dw2[36];
    __shared__ __align__(16) ull   s_pw2[32];
    // compose scratch (block 0 only)
    __shared__ float s_k2s[72];
    __shared__ float s_k0[200];
    __shared__ float s_k1[1600];
    __shared__ float s_K01[648];

    const int b = blockIdx.z;
    const int x0 = blockIdx.x * 32, y0 = blockIdx.y * 32;
    const int tid = threadIdx.x;

    // ---- compose (one block): k0 o k1 o sum16(k2) -> g_kc (11x11), k2 sum -> g_k2s ----
    if (blockIdx.x == 0 && blockIdx.y == 0 && blockIdx.z == 0) {
        for (int i = tid; i < 200; i += 256) s_k0[i] = k0[i];
        for (int i = tid; i < 1600; i += 256) s_k1[i] = k1[i];
        if (tid < 72) {
            float s = 0.f;
#pragma unroll
            for (int o = 0; o < 16; ++o) s += k2[tid * 16 + o];
            s_k2s[tid] = s;
            g_k2s[tid] = s;
        }
        __syncthreads();

        for (int i = tid; i < 648; i += 256) {
            int c2 = i & 7;
            int rx = (i >> 3) % 9;
            int ry = i / 72;
            float v = 0.f;
            int sy0 = ry - 4 > 0 ? ry - 4 : 0, sy1 = ry < 4 ? ry : 4;
            int sx0 = rx - 4 > 0 ? rx - 4 : 0, sx1 = rx < 4 ? rx : 4;
            for (int sy = sy0; sy <= sy1; ++sy)
                for (int sx = sx0; sx <= sx1; ++sx) {
                    int ty = ry - sy, txx = rx - sx;
#pragma unroll
                    for (int c1 = 0; c1 < 8; ++c1)
                        v += s_k0[(sy * 5 + sx) * 8 + c1] *
                             s_k1[((ty * 5 + txx) * 8 + c1) * 8 + c2];
                }
            s_K01[(ry * 9 + rx) * 8 + c2] = v;
        }
        __syncthreads();

        if (tid < 121) {
            int fx = tid % 11, fy = tid / 11;
            float v = 0.f;
            int ry0 = fy - 2 > 0 ? fy - 2 : 0, ry1 = fy < 8 ? fy : 8;
            int rx0 = fx - 2 > 0 ? fx - 2 : 0, rx1 = fx < 8 ? fx : 8;
            for (int ry = ry0; ry <= ry1; ++ry)
                for (int rx = rx0; rx <= rx1; ++rx) {
                    int vy = fy - ry, vx = fx - rx;
#pragma unroll
                    for (int c2 = 0; c2 < 8; ++c2)
                        v += s_K01[(ry * 9 + rx) * 8 + c2] *
                             s_k2s[(vy * 3 + vx) * 8 + c2];
                }
            g_kc[tid] = v;
        }
        __syncthreads();
    }

    // ---- edges tile ----
    if (tid < 36) {
        float2 v = ((const float2*)dw)[tid];
        s_dw2[tid] = pack2(v.x, v.y);
    }
    if (tid >= 64 && tid < 96) {
        float2 v = ((const float2*)pw)[tid - 64];
        s_pw2[tid - 64] = pack2(v.x, v.y);
    }
    for (int i = tid; i < 34 * 34; i += 256) {
        int r = i / 34, c = i % 34;
        int gy = y0 - 1 + r, gx = x0 - 1 + c;
        float v = 0.f;
        if (gy >= 0 && gy < H && gx >= 0 && gx < W)
            v = image[((b * H) + gy) * W + gx];
        s_img[i] = v;
    }
    __syncthreads();

    for (int i = tid; i < 32 * 32; i += 256) {
        int r = i >> 5, c = i & 31;
        ull e1p[4] = {0ull, 0ull, 0ull, 0ull};
#pragma unroll
        for (int t = 0; t < 9; ++t) {
            float v = s_img[(r + t / 3) * 34 + c + t % 3];
            ull vv = pack2(v, v);
            fma2(e1p[0], vv, s_dw2[t * 4 + 0]);
            fma2(e1p[1], vv, s_dw2[t * 4 + 1]);
            fma2(e1p[2], vv, s_dw2[t * 4 + 2]);
            fma2(e1p[3], vv, s_dw2[t * 4 + 3]);
        }
        ull e2p[4] = {0ull, 0ull, 0ull, 0ull};
#pragma unroll
        for (int j = 0; j < 4; ++j) {
            float2 e = unpack2(e1p[j]);
            ull sa = pack2(e.x, e.x);
            ull sb = pack2(e.y, e.y);
            const int ca = (2 * j) * 4, cb = (2 * j + 1) * 4;
            fma2(e2p[0], sa, s_pw2[ca + 0]);
            fma2(e2p[1], sa, s_pw2[ca + 1]);
            fma2(e2p[2], sa, s_pw2[ca + 2]);
            fma2(e2p[3], sa, s_pw2[ca + 3]);
            fma2(e2p[0], sb, s_pw2[cb + 0]);
            fma2(e2p[1], sb, s_pw2[cb + 1]);
            fma2(e2p[2], sb, s_pw2[cb + 2]);
            fma2(e2p[3], sb, s_pw2[cb + 3]);
        }
        float s = 0.f;
#pragma unroll
        for (int k = 0; k < 4; ++k) {
            float2 rr = unpack2(e2p[k]);
            s += fmaxf(rr.x, 0.f) + fmaxf(rr.y, 0.f);
        }
        g_edges[((b * H) + (y0 + r)) * W + (x0 + c)] = __fdividef(s, 1.f + fabsf(s));
    }
}

// ================= kpre + band merged kernel =================

// --- band role: staged-exact u -> c0 -> c1 -> c2k*kap, writes dist<=2 px ---
__device__ void role_band(const float* __restrict__ u,
                          const float* __restrict__ k0,
                          const float* __restrict__ k1,
                          const float* __restrict__ kap,
                          float* s_u, ull* s_w0, float* s_w1, float* s_k2,
                          float* s_c0, float* s_c1,
                          int b, int seg_id) {
    int oy0, ox0, oR, oC;
    band_region(seg_id, 3, oy0, ox0, oR, oC);
    const int RWu = oC + 10;
    const int RW0 = oC + 6;
    const int RW1 = oC + 2;
    const int Nu = (oR + 10) * RWu;   // 546
    const int N0 = (oR + 6) * RW0;    // 342
    const int N1 = (oR + 2) * RW1;    // 170
    const int tid = threadIdx.x;

    for (int i = tid; i < 100; i += 256) {
        float2 w = ((const float2*)k0)[i];
        s_w0[i] = pack2(w.x, w.y);
    }
    for (int i = tid; i < 1600; i += 256) s_w1[i] = k1[i];
    for (int i = tid; i < 72; i += 256) s_k2[i] = g_k2s[i];
    for (int i = tid; i < Nu; i += 256) {
        int r = i / RWu, c = i % RWu;
        int gy = oy0 - 5 + r, gx = ox0 - 5 + c;
        float v = 0.f;
        if (gy >= 0 && gy < H && gx >= 0 && gx < W)
            v = u[((b * H) + gy) * W + gx];
        s_u[i] = v;
    }
    __syncthreads();

    for (int i = tid; i < N0; i += 256) {
        int r = i / RW0, c = i % RW0;
        int gy = oy0 - 3 + r, gx = ox0 - 3 + c;
        ull acc[4] = {0ull, 0ull, 0ull, 0ull};
        if (gy >= 0 && gy < H && gx >= 0 && gx < W) {
#pragma unroll 1
            for (int t = 0; t < 25; ++t) {
                int dy = t / 5, dx = t % 5;
                float v = s_u[(r + dy) * RWu + c + dx];
                ull vv = pack2(v, v);
                fma2(acc[0], vv, s_w0[t * 4 + 0]);
                fma2(acc[1], vv, s_w0[t * 4 + 1]);
                fma2(acc[2], vv, s_w0[t * 4 + 2]);
                fma2(acc[3], vv, s_w0[t * 4 + 3]);
            }
        }
        float2 a0 = unpack2(acc[0]);
        float2 a1 = unpack2(acc[1]);
        float2 a2 = unpack2(acc[2]);
        float2 a3 = unpack2(acc[3]);
        s_c0[0 * 342 + i] = a0.x;  s_c0[1 * 342 + i] = a0.y;
        s_c0[2 * 342 + i] = a1.x;  s_c0[3 * 342 + i] = a1.y;
        s_c0[4 * 342 + i] = a2.x;  s_c0[5 * 342 + i] = a2.y;
        s_c0[6 * 342 + i] = a3.x;  s_c0[7 * 342 + i] = a3.y;
    }
    __syncthreads();

    for (int i = tid; i < N1; i += 256) {
        int r = i / RW1, c = i % RW1;
        int gy = oy0 - 1 + r, gx = ox0 - 1 + c;
        ull acc[4] = {0ull, 0ull, 0ull, 0ull};
        if (gy >= 0 && gy < H && gx >= 0 && gx < W) {
#pragma unroll 1
            for (int t = 0; t < 25; ++t) {
                int dy = t / 5, dx = t % 5;
                const float* wp = s_w1 + t * 64;
                const int base = (r + dy) * RW0 + c + dx;
#pragma unroll
                for (int ci = 0; ci < 8; ++ci) {
                    ulonglong2 wA = *(const ulonglong2*)(wp + ci * 8);
                    ulonglong2 wB = *(const ulonglong2*)(wp + ci * 8 + 4);
                    float v = s_c0[ci * 342 + base];
                    ull p = pack2(v, v);
                    fma2(acc[0], p, wA.x); fma2(acc[1], p, wA.y);
                    fma2(acc[2], p, wB.x); fma2(acc[3], p, wB.y);
                }
            }
        }
        float2 a0 = unpack2(acc[0]);
        float2 a1 = unpack2(acc[1]);
        float2 a2 = unpack2(acc[2]);
        float2 a3 = unpack2(acc[3]);
        s_c1[0 * 170 + i] = a0.x;  s_c1[1 * 170 + i] = a0.y;
        s_c1[2 * 170 + i] = a1.x;  s_c1[3 * 170 + i] = a1.y;
        s_c1[4 * 170 + i] = a2.x;  s_c1[5 * 170 + i] = a2.y;
        s_c1[6 * 170 + i] = a3.x;  s_c1[7 * 170 + i] = a3.y;
    }
    __syncthreads();

    for (int i = tid; i < oR * oC; i += 256) {
        int r = i / oC, c = i % oC;
        float acc = 0.f;
#pragma unroll
        for (int t = 0; t < 9; ++t) {
            int dy = t / 3, dx = t % 3;
            const int idx = (r + dy) * RW1 + c + dx;
#pragma unroll
            for (int ci = 0; ci < 8; ++ci)
                acc = fmaf(s_c1[ci * 170 + idx], s_k2[t * 8 + ci], acc);
        }
        int y = oy0 + r, x = ox0 + c;
        g_kpre[((b * H) + y) * W + x] = acc * kap[y * W + x];
    }
}

// --- kpre role: conv11x11(u, g_kc) * kap; skips dist<=2 border px (band owns them) ---
__device__ void role_kpre(const float* __restrict__ u,
                          const float* __restrict__ kap,
                          float* s_t, ull* s_K2,
                          int b, int x0, int y0) {
    const int tid = threadIdx.x;

    for (int i = tid; i < 121; i += 256) {
        float w = g_kc[i];
        s_K2[i] = pack2(w, w);
    }
    for (int i = tid; i < 42 * 42; i += 256) {
        int r = i / 42, c = i % 42;
        int gy = y0 - 5 + r, gx = x0 - 5 + c;
        float v = 0.f;
        if (gy >= 0 && gy < H && gx >= 0 && gx < W)
            v = u[((b * H) + gy) * W + gx];
        s_t[i] = v;
    }
    __syncthreads();

    const int tx = tid & 31, ty = tid >> 5;
    const int r0 = ty * 4;

    ull acc[2] = {0ull, 0ull};

#pragma unroll 1
    for (int dx = 0; dx < 11; ++dx) {
        float t[14];
        const float* col = s_t + r0 * 42 + tx + dx;
#pragma unroll
        for (int i = 0; i < 14; ++i) t[i] = col[i * 42];
        ull pk[13];
#pragma unroll
        for (int i = 0; i < 13; ++i) pk[i] = pack2(t[i], t[i + 1]);
#pragma unroll
        for (int dy = 0; dy < 11; ++dy) {
            ull w = s_K2[dy * 11 + dx];
            fma2(acc[0], pk[dy],     w);
            fma2(acc[1], pk[dy + 2], w);
        }
    }

    const int x = x0 + tx;
    const bool xin = (x >= 3) && (x < W - 3);
#pragma unroll
    for (int p = 0; p < 2; ++p) {
        float2 r = unpack2(acc[p]);
        int y = y0 + r0 + 2 * p;
        if (xin && y >= 3 && y < H - 3)
            g_kpre[((b * H) + y) * W + x] = r.x * kap[y * W + x];
        if (xin && y + 1 >= 3 && y + 1 < H - 3)
            g_kpre[((b * H) + y + 1) * W + x] = r.y * kap[(y + 1) * W + x];
    }
}

// ---------------- kernel 2: kpre (256 tiles) + band (64 segs, placed FIRST) per batch ----------------
__global__ void __launch_bounds__(256, 2)
k_kpre_band(const float* __restrict__ u,
            const float* __restrict__ k0,
            const float* __restrict__ k1,
            const float* __restrict__ kap) {
    // band smem
    __shared__ __align__(16) float s_u[546];
    __shared__ __align__(16) ull   s_w0[100];
    __shared__ __align__(16) float s_w1[1600];
    __shared__ float s_k2[72];
    __shared__ __align__(16) float s_c0[8 * 342];
    __shared__ __align__(16) float s_c1[8 * 170];
    // kpre smem
    __shared__ __align__(16) float s_t[42 * 42];
    __shared__ __align__(16) ull   s_K2[121];

    const int b = blockIdx.y;
    const int id = blockIdx.x;

    if (id < 64) {
        role_band(u, k0, k1, kap, s_u, s_w0, s_w1, s_k2, s_c0, s_c1, b, id);
    } else {
        int t = id - 64;
        role_kpre(u, kap, s_t, s_K2, b, (t & 15) * 32, (t >> 4) * 32);
    }
}

// ---------------- kernel 3: grads (f32x2 px-pairs, LDS.128 co-pairs) ----------------
__global__ void __launch_bounds__(256, 3)
k_grad(const float* __restrict__ wx,   // (3,3,1,32) -> [t*32+co]
       const float* __restrict__ wy) {
    __shared__ __align__(16) ull s_e2[26 * 34];   // edges pairs (gy, gy+8), origin y0-1
    __shared__ __align__(16) ull s_wx2[288];
    __shared__ __align__(16) ull s_wy2[288];

    const int b = blockIdx.z;
    const int x0 = blockIdx.x * 32, y0 = blockIdx.y * 32;
    const int tid = threadIdx.x;

    for (int i = tid; i < 288; i += 256) {
        float a = wx[i], c = wy[i];
        s_wx2[i] = pack2(a, a);
        s_wy2[i] = pack2(c, c);
    }
    // edges pairs: lanes = (gy, gy+8); zero outside image (reference zero-pads edges)
    for (int i = tid; i < 26 * 34; i += 256) {
        int r = i / 34, c = i % 34;
        int gy = y0 - 1 + r, gx = x0 - 1 + c;
        float e0 = 0.f, e1 = 0.f;
        if (gx >= 0 && gx < W) {
            if (gy >= 0 && gy < H)         e0 = g_edges[((b * H) + gy) * W + gx];
            if (gy + 8 >= 0 && gy + 8 < H) e1 = g_edges[((b * H) + gy + 8) * W + gx];
        }
        s_e2[i] = pack2(e0, e1);
    }
    __syncthreads();

    const int tx = tid & 31, ty = tid >> 5;  // ty 0..7
    // pair A: rows (ty, ty+8); pair B: rows (ty+16, ty+24)

    ull tapA[9], tapB[9];
#pragma unroll
    for (int t = 0; t < 9; ++t) {
        tapA[t] = s_e2[(ty + t / 3) * 34 + tx + t % 3];
        tapB[t] = s_e2[(ty + 16 + t / 3) * 34 + tx + t % 3];
    }

    float gxA0 = 0.f, gxA1 = 0.f, gyA0 = 0.f, gyA1 = 0.f;
    float gxB0 = 0.f, gxB1 = 0.f, gyB0 = 0.f, gyB1 = 0.f;
#pragma unroll 1
    for (int co = 0; co < 32; co += 2) {
        ull axA0 = 0ull, axA1 = 0ull, ayA0 = 0ull, ayA1 = 0ull;
        ull axB0 = 0ull, axB1 = 0ull, ayB0 = 0ull, ayB1 = 0ull;
#pragma unroll
        for (int t = 0; t < 9; ++t) {
            ulonglong2 wxp = *(const ulonglong2*)(s_wx2 + t * 32 + co);
            ulonglong2 wyp = *(const ulonglong2*)(s_wy2 + t * 32 + co);
            fma2(axA0, tapA[t], wxp.x);
            fma2(axA1, tapA[t], wxp.y);
            fma2(ayA0, tapA[t], wyp.x);
            fma2(ayA1, tapA[t], wyp.y);
            fma2(axB0, tapB[t], wxp.x);
            fma2(axB1, tapB[t], wxp.y);
            fma2(ayB0, tapB[t], wyp.x);
            fma2(ayB1, tapB[t], wyp.y);
        }
        float2 r0, r1;
        r0 = unpack2(axA0); r1 = unpack2(axA1);
        gxA0 += fmaxf(r0.x, 0.f) + fmaxf(r1.x, 0.f);
        gxA1 += fmaxf(r0.y, 0.f) + fmaxf(r1.y, 0.f);
        r0 = unpack2(ayA0); r1 = unpack2(ayA1);
        gyA0 += fmaxf(r0.x, 0.f) + fmaxf(r1.x, 0.f);
        gyA1 += fmaxf(r0.y, 0.f) + fmaxf(r1.y, 0.f);
        r0 = unpack2(axB0); r1 = unpack2(axB1);
        gxB0 += fmaxf(r0.x, 0.f) + fmaxf(r1.x, 0.f);
        gxB1 += fmaxf(r0.y, 0.f) + fmaxf(r1.y, 0.f);
        r0 = unpack2(ayB0); r1 = unpack2(ayB1);
        gyB0 += fmaxf(r0.x, 0.f) + fmaxf(r1.x, 0.f);
        gyB1 += fmaxf(r0.y, 0.f) + fmaxf(r1.y, 0.f);
    }

    const float gxv[4] = {gxA0, gxA1, gxB0, gxB1};
    const float gyv[4] = {gyA0, gyA1, gyB0, gyB1};
#pragma unroll
    for (int k = 0; k < 4; ++k) {
        const int py = ty + 8 * k;
        g_gxy[((b * H) + (y0 + py)) * W + (x0 + tx)] = pack2(gxv[k], gyv[k]);
    }
}

// ---------------- kernel 4: final-lite: diffs + smoother + sum ----------------
__global__ void __launch_bounds__(256, 3)
k_final(const float* __restrict__ u,
        const float* __restrict__ ws,  // (5,5,1,1)
        float* __restrict__ out) {
    __shared__ __align__(16) float s_u[34 * 34];
    __shared__ __align__(16) ull   s_kp2[28 * 36];
    __shared__ __align__(16) ull   s_ws2[25];

    const int b = blockIdx.z;
    const int x0 = blockIdx.x * 32, y0 = blockIdx.y * 32;
    const int tid = threadIdx.x;

    if (tid < 25) {
        float w = ws[tid];
        s_ws2[tid] = pack2(w, w);
    }
    for (int i = tid; i < 34 * 34; i += 256) {
        int r = i / 34, c = i % 34;
        int gy = y0 - 1 + r, gx = x0 - 1 + c;
        float v = 0.f;
        if (gy >= 0 && gy < H && gx >= 0 && gx < W)
            v = u[((b * H) + gy) * W + gx];
        s_u[i] = v;
    }
    for (int i = tid; i < 28 * 36; i += 256) {
        int r = i / 36, c = i % 36;
        int gy = y0 - 2 + r, gx = x0 - 2 + c;
        float p0 = 0.f, p1 = 0.f;
        if (gx >= 0 && gx < W) {
            if (gy >= 0 && gy < H)         p0 = g_kpre[((b * H) + gy) * W + gx];
            if (gy + 8 >= 0 && gy + 8 < H) p1 = g_kpre[((b * H) + gy + 8) * W + gx];
        }
        s_kp2[i] = pack2(p0, p1);
    }
    __syncthreads();

    const int tx = tid & 31, ty = tid >> 5;

    ull kaccA = 0ull, kaccB = 0ull;
#pragma unroll
    for (int t = 0; t < 25; ++t) {
        ull w = s_ws2[t];
        fma2(kaccA, s_kp2[(ty + t / 5) * 36 + tx + t % 5], w);
        fma2(kaccB, s_kp2[(ty + 16 + t / 5) * 36 + tx + t % 5], w);
    }
    float2 kpA = unpack2(kaccA), kpB = unpack2(kaccB);
    const float kvv[4] = {kpA.x, kpA.y, kpB.x, kpB.y};

#pragma unroll
    for (int k = 0; k < 4; ++k) {
        const int py = ty + 8 * k;
        const int gidx = ((b * H) + (y0 + py)) * W + (x0 + tx);
        const int ec = (py + 1) * 34 + tx + 1;
        float uc = s_u[ec];
        float xp = uc - s_u[ec - 1];
        float yp = uc - s_u[ec + 34];

        float2 g = unpack2(g_gxy[gidx]);
        float ev = g_edges[gidx];

        // fxn = fyn = 0 exactly (gx, gy are sums of relus)
        out[gidx] = uc + g.x * xp + g.y * yp + ev + kvv[k];
    }
}

// ---------------- launch ----------------
extern "C" void kernel_launch(void* const* d_in, const int* in_sizes, int n_in,
                              void* d_out, int out_size) {
    (void)in_sizes; (void)n_in; (void)out_size;
    const float* u     = (const float*)d_in[0];
    const float* image = (const float*)d_in[1];
    const float* wx    = (const float*)d_in[2];
    const float* wy    = (const float*)d_in[3];
    const float* dw    = (const float*)d_in[4];
    const float* pw    = (const float*)d_in[5];
    const float* k0    = (const float*)d_in[6];
    const float* k1    = (const float*)d_in[7];
    const float* k2    = (const float*)d_in[8];
    const float* ws    = (const float*)d_in[9];
    const float* kap   = (const float*)d_in[10];
    float* out = (float*)d_out;

    dim3 gridT(W / 32, H / 32, B);

    k_edges<<<gridT, dim3(256)>>>(image, dw, pw, k0, k1, k2);     // + compose in block 0
    k_kpre_band<<<dim3(320, B), dim3(256)>>>(u, k0, k1, kap);     // band blocks first, kpre after
    k_grad<<<gridT, dim3(256)>>>(wx, wy);
    k_final<<<gridT, dim3(256)>>>(u, ws, out);
}

// round 14
// speedup vs baseline: 1.4597x; 1.4474x over previous
#include <cuda_runtime.h>
#include <cstdint>

typedef unsigned long long ull;

#define B 8
#define H 512
#define W 512

// ---------------- device scratch (allocation-free) ----------------
__device__ float g_kpre[B * H * W];
__device__ float g_edges[B * H * W];
__device__ float g_k2s[72];
__device__ float g_kc[121];

// ---------------- f32x2 packed helpers (sm_100+) ----------------
__device__ __forceinline__ ull pack2(float lo, float hi) {
    ull r;
    asm("mov.b64 %0, {%1, %2};" : "=l"(r) : "f"(lo), "f"(hi));
    return r;
}
__device__ __forceinline__ float2 unpack2(ull v) {
    float2 r;
    asm("mov.b64 {%0, %1}, %2;" : "=f"(r.x), "=f"(r.y) : "l"(v));
    return r;
}
__device__ __forceinline__ void fma2(ull& acc, ull a, ull b) {
    asm("fma.rn.f32x2 %0, %1, %2, %0;" : "+l"(acc) : "l"(a), "l"(b));
}

// ---------------- border band decode: 64 segs/batch, 32-px segments, bw=3 ----------------
__device__ __forceinline__ void band_region(int id, int bw,
                                            int& oy0, int& ox0, int& oR, int& oC) {
    int seg = id >> 4, s = id & 15;
    if (seg == 0)      { oy0 = 0;      ox0 = 32 * s; oR = bw; oC = 32; }
    else if (seg == 1) { oy0 = H - bw; ox0 = 32 * s; oR = bw; oC = 32; }
    else if (seg == 2) { oy0 = 32 * s; ox0 = 0;      oR = 32; oC = bw; }
    else               { oy0 = 32 * s; ox0 = W - bw; oR = 32; oC = bw; }
}

// ---------------- kernel: compose k0 o k1 o sum16(k2) -> 11x11 (smem-staged) ----------------
__global__ void k_compose(const float* __restrict__ k0,
                          const float* __restrict__ k1,
                          const float* __restrict__ k2) {
    __shared__ float s_k2s[72];
    __shared__ float s_k0[200];
    __shared__ float s_k1[1600];
    __shared__ float s_K01[648]; // [ry(9)][rx(9)][c2(8)]
    const int tid = threadIdx.x;

    for (int i = tid; i < 200; i += 648) s_k0[i] = k0[i];
    for (int i = tid; i < 1600; i += 648) s_k1[i] = k1[i];
    if (tid < 72) {
        float s = 0.f;
#pragma unroll
        for (int o = 0; o < 16; ++o) s += k2[tid * 16 + o];
        s_k2s[tid] = s;
        g_k2s[tid] = s;
    }
    __syncthreads();

    if (tid < 648) {
        int c2 = tid & 7;
        int rx = (tid >> 3) % 9;
        int ry = tid / 72;
        float v = 0.f;
        int sy0 = ry - 4 > 0 ? ry - 4 : 0, sy1 = ry < 4 ? ry : 4;
        int sx0 = rx - 4 > 0 ? rx - 4 : 0, sx1 = rx < 4 ? rx : 4;
        for (int sy = sy0; sy <= sy1; ++sy)
            for (int sx = sx0; sx <= sx1; ++sx) {
                int ty = ry - sy, txx = rx - sx;
#pragma unroll
                for (int c1 = 0; c1 < 8; ++c1)
                    v += s_k0[(sy * 5 + sx) * 8 + c1] *
                         s_k1[((ty * 5 + txx) * 8 + c1) * 8 + c2];
            }
        s_K01[(ry * 9 + rx) * 8 + c2] = v;
    }
    __syncthreads();

    if (tid < 121) {
        int fx = tid % 11, fy = tid / 11;
        float v = 0.f;
        int ry0 = fy - 2 > 0 ? fy - 2 : 0, ry1 = fy < 8 ? fy : 8;
        int rx0 = fx - 2 > 0 ? fx - 2 : 0, rx1 = fx < 8 ? fx : 8;
        for (int ry = ry0; ry <= ry1; ++ry)
            for (int rx = rx0; rx <= rx1; ++rx) {
                int vy = fy - ry, vx = fx - rx;
#pragma unroll
                for (int c2 = 0; c2 < 8; ++c2)
                    v += s_K01[(ry * 9 + rx) * 8 + c2] *
                         s_k2s[(vy * 3 + vx) * 8 + c2];
            }
        g_kc[tid] = v;
    }
}

// ---------------- kernel: edges = softsign(sum_co relu(pw(dw(image)))) ----------------
__global__ void __launch_bounds__(256, 3)
k_edges(const float* __restrict__ image,
        const float* __restrict__ dw,   // (3,3,1,8)
        const float* __restrict__ pw) { // (1,1,8,8)
    __shared__ __align__(16) float s_img[34 * 34];
    __shared__ __align__(16) ull   s_dw2[36];
    __shared__ __align__(16) ull   s_pw2[32];

    const int b = blockIdx.z;
    const int x0 = blockIdx.x * 32, y0 = blockIdx.y * 32;
    const int tid = threadIdx.x;

    if (tid < 36) {
        float2 v = ((const float2*)dw)[tid];
        s_dw2[tid] = pack2(v.x, v.y);
    }
    if (tid >= 64 && tid < 96) {
        float2 v = ((const float2*)pw)[tid - 64];
        s_pw2[tid - 64] = pack2(v.x, v.y);
    }
    for (int i = tid; i < 34 * 34; i += 256) {
        int r = i / 34, c = i % 34;
        int gy = y0 - 1 + r, gx = x0 - 1 + c;
        float v = 0.f;
        if (gy >= 0 && gy < H && gx >= 0 && gx < W)
            v = image[((b * H) + gy) * W + gx];
        s_img[i] = v;
    }
    __syncthreads();

    for (int i = tid; i < 32 * 32; i += 256) {
        int r = i >> 5, c = i & 31;
        ull e1p[4] = {0ull, 0ull, 0ull, 0ull};
#pragma unroll
        for (int t = 0; t < 9; ++t) {
            float v = s_img[(r + t / 3) * 34 + c + t % 3];
            ull vv = pack2(v, v);
            fma2(e1p[0], vv, s_dw2[t * 4 + 0]);
            fma2(e1p[1], vv, s_dw2[t * 4 + 1]);
            fma2(e1p[2], vv, s_dw2[t * 4 + 2]);
            fma2(e1p[3], vv, s_dw2[t * 4 + 3]);
        }
        ull e2p[4] = {0ull, 0ull, 0ull, 0ull};
#pragma unroll
        for (int j = 0; j < 4; ++j) {
            float2 e = unpack2(e1p[j]);
            ull sa = pack2(e.x, e.x);
            ull sb = pack2(e.y, e.y);
            const int ca = (2 * j) * 4, cb = (2 * j + 1) * 4;
            fma2(e2p[0], sa, s_pw2[ca + 0]);
            fma2(e2p[1], sa, s_pw2[ca + 1]);
            fma2(e2p[2], sa, s_pw2[ca + 2]);
            fma2(e2p[3], sa, s_pw2[ca + 3]);
            fma2(e2p[0], sb, s_pw2[cb + 0]);
            fma2(e2p[1], sb, s_pw2[cb + 1]);
            fma2(e2p[2], sb, s_pw2[cb + 2]);
            fma2(e2p[3], sb, s_pw2[cb + 3]);
        }
        float s = 0.f;
#pragma unroll
        for (int k = 0; k < 4; ++k) {
            float2 rr = unpack2(e2p[k]);
            s += fmaxf(rr.x, 0.f) + fmaxf(rr.y, 0.f);
        }
        g_edges[((b * H) + (y0 + r)) * W + (x0 + c)] = __fdividef(s, 1.f + fabsf(s));
    }
}

// ---------------- kernel: kpre = conv11x11(u, g_kc) * kappa_kernel ----------------
__global__ void __launch_bounds__(256, 3)
k_kpre(const float* __restrict__ u, const float* __restrict__ kap) {
    __shared__ __align__(16) float s_t[42 * 42];
    __shared__ __align__(16) ull   s_K2[121];

    const int b = blockIdx.z;
    const int x0 = blockIdx.x * 32, y0 = blockIdx.y * 32;
    const int tid = threadIdx.x;

    for (int i = tid; i < 121; i += 256) {
        float w = g_kc[i];
        s_K2[i] = pack2(w, w);
    }
    for (int i = tid; i < 42 * 42; i += 256) {
        int r = i / 42, c = i % 42;
        int gy = y0 - 5 + r, gx = x0 - 5 + c;
        float v = 0.f;
        if (gy >= 0 && gy < H && gx >= 0 && gx < W)
            v = u[((b * H) + gy) * W + gx];
        s_t[i] = v;
    }
    __syncthreads();

    const int tx = tid & 31, ty = tid >> 5;
    const int r0 = ty * 4;

    ull acc[2] = {0ull, 0ull};

#pragma unroll 1
    for (int dx = 0; dx < 11; ++dx) {
        float t[14];
        const float* col = s_t + r0 * 42 + tx + dx;
#pragma unroll
        for (int i = 0; i < 14; ++i) t[i] = col[i * 42];
        ull pk[13];
#pragma unroll
        for (int i = 0; i < 13; ++i) pk[i] = pack2(t[i], t[i + 1]);
#pragma unroll
        for (int dy = 0; dy < 11; ++dy) {
            ull w = s_K2[dy * 11 + dx];
            fma2(acc[0], pk[dy],     w);
            fma2(acc[1], pk[dy + 2], w);
        }
    }

    const int x = x0 + tx;
#pragma unroll
    for (int p = 0; p < 2; ++p) {
        float2 r = unpack2(acc[p]);
        int y = y0 + r0 + 2 * p;
        g_kpre[((b * H) + y) * W + x]     = r.x * kap[y * W + x];
        g_kpre[((b * H) + y + 1) * W + x] = r.y * kap[(y + 1) * W + x];
    }
}

// ---------------- fused band kernel: u -> c0 -> c1 -> c2k*kap in smem (band 3) ----------------
__global__ void __launch_bounds__(256, 2)
k_band(const float* __restrict__ u,
       const float* __restrict__ k0,
       const float* __restrict__ k1,
       const float* __restrict__ kap) {
    __shared__ __align__(16) float s_u[546];
    __shared__ __align__(16) ull   s_w0[100];
    __shared__ __align__(16) float s_w1[1600];
    __shared__ float s_k2[72];
    __shared__ __align__(16) float s_c0[8 * 342];
    __shared__ __align__(16) float s_c1[8 * 170];

    const int b = blockIdx.y;
    int oy0, ox0, oR, oC;
    band_region(blockIdx.x, 3, oy0, ox0, oR, oC);
    const int RWu = oC + 10;
    const int RW0 = oC + 6;
    const int RW1 = oC + 2;
    const int Nu = (oR + 10) * RWu;
    const int N0 = (oR + 6) * RW0;
    const int N1 = (oR + 2) * RW1;
    const int tid = threadIdx.x;

    for (int i = tid; i < 100; i += 256) {
        float2 w = ((const float2*)k0)[i];
        s_w0[i] = pack2(w.x, w.y);
    }
    for (int i = tid; i < 1600; i += 256) s_w1[i] = k1[i];
    for (int i = tid; i < 72; i += 256) s_k2[i] = g_k2s[i];
    for (int i = tid; i < Nu; i += 256) {
        int r = i / RWu, c = i % RWu;
        int gy = oy0 - 5 + r, gx = ox0 - 5 + c;
        float v = 0.f;
        if (gy >= 0 && gy < H && gx >= 0 && gx < W)
            v = u[((b * H) + gy) * W + gx];
        s_u[i] = v;
    }
    __syncthreads();

    for (int i = tid; i < N0; i += 256) {
        int r = i / RW0, c = i % RW0;
        int gy = oy0 - 3 + r, gx = ox0 - 3 + c;
        ull acc[4] = {0ull, 0ull, 0ull, 0ull};
        if (gy >= 0 && gy < H && gx >= 0 && gx < W) {
#pragma unroll 1
            for (int t = 0; t < 25; ++t) {
                int dy = t / 5, dx = t % 5;
                float v = s_u[(r + dy) * RWu + c + dx];
                ull vv = pack2(v, v);
                fma2(acc[0], vv, s_w0[t * 4 + 0]);
                fma2(acc[1], vv, s_w0[t * 4 + 1]);
                fma2(acc[2], vv, s_w0[t * 4 + 2]);
                fma2(acc[3], vv, s_w0[t * 4 + 3]);
            }
        }
        float2 a0 = unpack2(acc[0]);
        float2 a1 = unpack2(acc[1]);
        float2 a2 = unpack2(acc[2]);
        float2 a3 = unpack2(acc[3]);
        s_c0[0 * 342 + i] = a0.x;  s_c0[1 * 342 + i] = a0.y;
        s_c0[2 * 342 + i] = a1.x;  s_c0[3 * 342 + i] = a1.y;
        s_c0[4 * 342 + i] = a2.x;  s_c0[5 * 342 + i] = a2.y;
        s_c0[6 * 342 + i] = a3.x;  s_c0[7 * 342 + i] = a3.y;
    }
    __syncthreads();

    for (int i = tid; i < N1; i += 256) {
        int r = i / RW1, c = i % RW1;
        int gy = oy0 - 1 + r, gx = ox0 - 1 + c;
        ull acc[4] = {0ull, 0ull, 0ull, 0ull};
        if (gy >= 0 && gy < H && gx >= 0 && gx < W) {
#pragma unroll 1
            for (int t = 0; t < 25; ++t) {
                int dy = t / 5, dx = t % 5;
                const float* wp = s_w1 + t * 64;
                const int base = (r + dy) * RW0 + c + dx;
#pragma unroll
                for (int ci = 0; ci < 8; ++ci) {
                    ulonglong2 wA = *(const ulonglong2*)(wp + ci * 8);
                    ulonglong2 wB = *(const ulonglong2*)(wp + ci * 8 + 4);
                    float v = s_c0[ci * 342 + base];
                    ull p = pack2(v, v);
                    fma2(acc[0], p, wA.x); fma2(acc[1], p, wA.y);
                    fma2(acc[2], p, wB.x); fma2(acc[3], p, wB.y);
                }
            }
        }
        float2 a0 = unpack2(acc[0]);
        float2 a1 = unpack2(acc[1]);
        float2 a2 = unpack2(acc[2]);
        float2 a3 = unpack2(acc[3]);
        s_c1[0 * 170 + i] = a0.x;  s_c1[1 * 170 + i] = a0.y;
        s_c1[2 * 170 + i] = a1.x;  s_c1[3 * 170 + i] = a1.y;
        s_c1[4 * 170 + i] = a2.x;  s_c1[5 * 170 + i] = a2.y;
        s_c1[6 * 170 + i] = a3.x;  s_c1[7 * 170 + i] = a3.y;
    }
    __syncthreads();

    for (int i = tid; i < oR * oC; i += 256) {
        int r = i / oC, c = i % oC;
        float acc = 0.f;
#pragma unroll
        for (int t = 0; t < 9; ++t) {
            int dy = t / 3, dx = t % 3;
            const int idx = (r + dy) * RW1 + c + dx;
#pragma unroll
            for (int ci = 0; ci < 8; ++ci)
                acc = fmaf(s_c1[ci * 170 + idx], s_k2[t * 8 + ci], acc);
        }
        int y = oy0 + r, x = ox0 + c;
        g_kpre[((b * H) + y) * W + x] = acc * kap[y * W + x];
    }
}

// ---------------- fused grad+final: grads, then diffs + smoother + sum -> out ----------------
// Register discipline: the smoother/diff epilogue runs AFTER the grad taps die,
// so peak pressure stays at the grad loop (fits the (256,3) 85-reg cap).
__global__ void __launch_bounds__(256, 3)
k_gradfinal(const float* __restrict__ u,
            const float* __restrict__ wx,  // (3,3,1,32) -> [t*32+co]
            const float* __restrict__ wy,
            const float* __restrict__ ws,  // (5,5,1,1)
            float* __restrict__ out) {
    __shared__ __align__(16) ull   s_e2[26 * 34];   // edges pairs (gy, gy+8), origin y0-1
    __shared__ __align__(16) ull   s_kp2[28 * 36];  // kpre pairs (gy, gy+8), origin y0-2
    __shared__ __align__(16) float s_u[34 * 34];
    __shared__ __align__(16) ull   s_wx2[288];
    __shared__ __align__(16) ull   s_wy2[288];
    __shared__ __align__(16) ull   s_ws2[25];

    const int b = blockIdx.z;
    const int x0 = blockIdx.x * 32, y0 = blockIdx.y * 32;
    const int tid = threadIdx.x;

    for (int i = tid; i < 288; i += 256) {
        float a = wx[i], c = wy[i];
        s_wx2[i] = pack2(a, a);
        s_wy2[i] = pack2(c, c);
    }
    if (tid < 25) {
        float w = ws[tid];
        s_ws2[tid] = pack2(w, w);
    }
    for (int i = tid; i < 34 * 34; i += 256) {
        int r = i / 34, c = i % 34;
        int gy = y0 - 1 + r, gx = x0 - 1 + c;
        float v = 0.f;
        if (gy >= 0 && gy < H && gx >= 0 && gx < W)
            v = u[((b * H) + gy) * W + gx];
        s_u[i] = v;
    }
    // edges pairs: lanes = (gy, gy+8); zero outside image (reference zero-pads edges)
    for (int i = tid; i < 26 * 34; i += 256) {
        int r = i / 34, c = i % 34;
        int gy = y0 - 1 + r, gx = x0 - 1 + c;
        float e0 = 0.f, e1 = 0.f;
        if (gx >= 0 && gx < W) {
            if (gy >= 0 && gy < H)         e0 = g_edges[((b * H) + gy) * W + gx];
            if (gy + 8 >= 0 && gy + 8 < H) e1 = g_edges[((b * H) + gy + 8) * W + gx];
        }
        s_e2[i] = pack2(e0, e1);
    }
    // kpre pairs: lanes = (gy, gy+8)
    for (int i = tid; i < 28 * 36; i += 256) {
        int r = i / 36, c = i % 36;
        int gy = y0 - 2 + r, gx = x0 - 2 + c;
        float p0 = 0.f, p1 = 0.f;
        if (gx >= 0 && gx < W) {
            if (gy >= 0 && gy < H)         p0 = g_kpre[((b * H) + gy) * W + gx];
            if (gy + 8 >= 0 && gy + 8 < H) p1 = g_kpre[((b * H) + gy + 8) * W + gx];
        }
        s_kp2[i] = pack2(p0, p1);
    }
    __syncthreads();

    const int tx = tid & 31, ty = tid >> 5;  // ty 0..7
    // pair A: rows (ty, ty+8); pair B: rows (ty+16, ty+24)

    // ---- phase 1: gradient convs ----
    ull tapA[9], tapB[9];
#pragma unroll
    for (int t = 0; t < 9; ++t) {
        tapA[t] = s_e2[(ty + t / 3) * 34 + tx + t % 3];
        tapB[t] = s_e2[(ty + 16 + t / 3) * 34 + tx + t % 3];
    }

    float gxA0 = 0.f, gxA1 = 0.f, gyA0 = 0.f, gyA1 = 0.f;
    float gxB0 = 0.f, gxB1 = 0.f, gyB0 = 0.f, gyB1 = 0.f;
#pragma unroll 1
    for (int co = 0; co < 32; co += 2) {
        ull axA0 = 0ull, axA1 = 0ull, ayA0 = 0ull, ayA1 = 0ull;
        ull axB0 = 0ull, axB1 = 0ull, ayB0 = 0ull, ayB1 = 0ull;
#pragma unroll
        for (int t = 0; t < 9; ++t) {
            ulonglong2 wxp = *(const ulonglong2*)(s_wx2 + t * 32 + co);
            ulonglong2 wyp = *(const ulonglong2*)(s_wy2 + t * 32 + co);
            fma2(axA0, tapA[t], wxp.x);
            fma2(axA1, tapA[t], wxp.y);
            fma2(ayA0, tapA[t], wyp.x);
            fma2(ayA1, tapA[t], wyp.y);
            fma2(axB0, tapB[t], wxp.x);
            fma2(axB1, tapB[t], wxp.y);
            fma2(ayB0, tapB[t], wyp.x);
            fma2(ayB1, tapB[t], wyp.y);
        }
        float2 r0, r1;
        r0 = unpack2(axA0); r1 = unpack2(axA1);
        gxA0 += fmaxf(r0.x, 0.f) + fmaxf(r1.x, 0.f);
        gxA1 += fmaxf(r0.y, 0.f) + fmaxf(r1.y, 0.f);
        r0 = unpack2(ayA0); r1 = unpack2(ayA1);
        gyA0 += fmaxf(r0.x, 0.f) + fmaxf(r1.x, 0.f);
        gyA1 += fmaxf(r0.y, 0.f) + fmaxf(r1.y, 0.f);
        r0 = unpack2(axB0); r1 = unpack2(axB1);
        gxB0 += fmaxf(r0.x, 0.f) + fmaxf(r1.x, 0.f);
        gxB1 += fmaxf(r0.y, 0.f) + fmaxf(r1.y, 0.f);
        r0 = unpack2(ayB0); r1 = unpack2(ayB1);
        gyB0 += fmaxf(r0.x, 0.f) + fmaxf(r1.x, 0.f);
        gyB1 += fmaxf(r0.y, 0.f) + fmaxf(r1.y, 0.f);
    }

    // ---- phase 2: smoother conv (taps dead now) ----
    ull kaccA = 0ull, kaccB = 0ull;
#pragma unroll
    for (int t = 0; t < 25; ++t) {
        ull w = s_ws2[t];
        fma2(kaccA, s_kp2[(ty + t / 5) * 36 + tx + t % 5], w);
        fma2(kaccB, s_kp2[(ty + 16 + t / 5) * 36 + tx + t % 5], w);
    }
    float2 kpA = unpack2(kaccA), kpB = unpack2(kaccB);
    float2 eA = unpack2(s_e2[(ty + 1) * 34 + tx + 1]);
    float2 eB = unpack2(s_e2[(ty + 17) * 34 + tx + 1]);

    const float gxv[4] = {gxA0, gxA1, gxB0, gxB1};
    const float gyv[4] = {gyA0, gyA1, gyB0, gyB1};
    const float evv[4] = {eA.x, eA.y, eB.x, eB.y};
    const float kvv[4] = {kpA.x, kpA.y, kpB.x, kpB.y};

    // ---- phase 3: diffs + sum ----
#pragma unroll
    for (int k = 0; k < 4; ++k) {
        const int py = ty + 8 * k;   // rows ty, ty+8, ty+16, ty+24
        const int ec = (py + 1) * 34 + tx + 1;
        float uc = s_u[ec];
        float xp = uc - s_u[ec - 1];    // u[x] - u[x-1]
        float yp = uc - s_u[ec + 34];   // u[y] - u[y+1]

        // fxn = fyn = 0 exactly (gx, gy are sums of relus)
        out[((b * H) + (y0 + py)) * W + (x0 + tx)] =
            uc + gxv[k] * xp + gyv[k] * yp + evv[k] + kvv[k];
    }
}

// ---------------- launch ----------------
extern "C" void kernel_launch(void* const* d_in, const int* in_sizes, int n_in,
                              void* d_out, int out_size) {
    (void)in_sizes; (void)n_in; (void)out_size;
    const float* u     = (const float*)d_in[0];
    const float* image = (const float*)d_in[1];
    const float* wx    = (const float*)d_in[2];
    const float* wy    = (const float*)d_in[3];
    const float* dw    = (const float*)d_in[4];
    const float* pw    = (const float*)d_in[5];
    const float* k0    = (const float*)d_in[6];
    const float* k1    = (const float*)d_in[7];
    const float* k2    = (const float*)d_in[8];
    const float* ws    = (const float*)d_in[9];
    const float* kap   = (const float*)d_in[10];
    float* out = (float*)d_out;

    dim3 gridT(W / 32, H / 32, B);

    k_compose<<<1, 648>>>(k0, k1, k2);
    k_edges<<<gridT, dim3(256)>>>(image, dw, pw);
    k_kpre<<<gridT, dim3(256)>>>(u, kap);
    k_band<<<dim3(64, B), dim3(256)>>>(u, k0, k1, kap);
    k_gradfinal<<<gridT, dim3(256)>>>(u, wx, wy, ws, out);
}